// round 5
// baseline (speedup 1.0000x reference)
#include <cuda_runtime.h>
#include <math.h>

#define BATCH 8
#define CH    2048
#define HW    4096
#define NBC   (BATCH*CH)
#define NSEL  (CH*3)

__device__ float   g_stats[BATCH][CH][3];
__device__ float   g_gate[BATCH][CH];
__device__ unsigned g_cnt = 0;
__device__ unsigned g_gen = 0;

struct SMed { unsigned keys[NSEL]; unsigned hist[16][256]; };   // 40960 B
union  SU   { SMed med; float red[8][4][3]; };

// ---------------------------------------------------------------------------
// Device-wide software barrier (grid sized to guaranteed residency).
// ---------------------------------------------------------------------------
__device__ __forceinline__ void gbar(int G) {
    __syncthreads();
    if (threadIdx.x == 0) {
        __threadfence();
        unsigned my = atomicAdd(&g_gen, 0u);
        if (atomicAdd(&g_cnt, 1u) == (unsigned)(G - 1)) {
            g_cnt = 0;
            __threadfence();
            atomicAdd(&g_gen, 1u);
        } else {
            while (atomicAdd(&g_gen, 0u) == my) { __nanosleep(64); }
        }
        __threadfence();
    }
    __syncthreads();
}

// ---------------------------------------------------------------------------
// Stats for channels [c0 .. c0+7] of batch b: 128 threads per channel,
// 8 float4 per thread (MLP=8).  red[grp][warpInGrp][{s,s2,mx}]
// ---------------------------------------------------------------------------
__device__ __forceinline__ void stats_tile(const float* __restrict__ x, int b,
                                           int c0, float (*red)[4][3]) {
    int tid = threadIdx.x;
    int grp = tid >> 7;            // 0..7  (channel within tile)
    int sub = tid & 127;           // position group
    int c   = c0 + grp;
    float s = 0.f, s2 = 0.f, mx = -INFINITY;
    if (c < CH) {
        const float4* p = reinterpret_cast<const float4*>(x)
                        + ((size_t)(b * CH + c)) * (HW / 4);
#pragma unroll
        for (int j = 0; j < 8; j++) {
            float4 v = p[sub + 128 * j];
            s  += (v.x + v.y) + (v.z + v.w);
            s2 += (v.x * v.x + v.y * v.y) + (v.z * v.z + v.w * v.w);
            mx = fmaxf(mx, fmaxf(fmaxf(v.x, v.y), fmaxf(v.z, v.w)));
        }
    }
#pragma unroll
    for (int o = 16; o; o >>= 1) {
        s  += __shfl_xor_sync(0xffffffffu, s, o);
        s2 += __shfl_xor_sync(0xffffffffu, s2, o);
        mx = fmaxf(mx, __shfl_xor_sync(0xffffffffu, mx, o));
    }
    int wig = (tid >> 5) & 3;      // warp within 128-thread group
    if ((tid & 31) == 0) { red[grp][wig][0] = s; red[grp][wig][1] = s2; red[grp][wig][2] = mx; }
    __syncthreads();
    if (sub == 0 && c < CH) {
        float S = 0.f, S2 = 0.f, M = -INFINITY;
#pragma unroll
        for (int j = 0; j < 4; j++) {
            S += red[grp][j][0]; S2 += red[grp][j][1]; M = fmaxf(M, red[grp][j][2]);
        }
        float mean = S / (float)HW;
        float var  = (S2 - (float)HW * mean * mean) / (float)(HW - 1);
        var = fmaxf(var, 0.f);
        g_stats[b][c][0] = mean;
        g_stats[b][c][1] = M;
        g_stats[b][c][2] = sqrtf(var);
    }
    __syncthreads();
}

// ---------------------------------------------------------------------------
// Median (exact, avg of ranks 3071/3072) + gate for batch b.  One block.
// ---------------------------------------------------------------------------
__device__ __forceinline__ unsigned f2k(float f) {
    unsigned u = __float_as_uint(f);
    return (u & 0x80000000u) ? ~u : (u | 0x80000000u);
}
__device__ __forceinline__ float k2f(unsigned k) {
    unsigned u = (k & 0x80000000u) ? (k ^ 0x80000000u) : ~k;
    return __uint_as_float(u);
}

__device__ void median_gate(int b, SMed* sh,
                            const float* __restrict__ cfc_w,
                            const float* __restrict__ bn_w,
                            const float* __restrict__ bn_b) {
    __shared__ unsigned s_prefix;
    __shared__ int      s_rank;
    __shared__ unsigned s_eq;
    __shared__ unsigned s_wmin[32];

    int tid = threadIdx.x, lane = tid & 31, warp = tid >> 5;
    const float* st = &g_stats[b][0][0];

    for (int i = tid; i < NSEL; i += 1024) sh->keys[i] = f2k(st[i]);
    __syncthreads();

    int rank = NSEL / 2 - 1;
    unsigned prefix = 0;
    for (int shift = 24; shift >= 0; shift -= 8) {
        for (int i = tid; i < 16 * 256; i += 1024) (&sh->hist[0][0])[i] = 0u;
        __syncthreads();
        unsigned mhi = (shift == 24) ? 0u : (0xFFFFFFFFu << (shift + 8));
        int grp = tid >> 6;
        for (int i = tid; i < NSEL; i += 1024) {
            unsigned k = sh->keys[i];
            if ((k & mhi) == prefix)
                atomicAdd(&sh->hist[grp][(k >> shift) & 255u], 1u);
        }
        __syncthreads();
        if (tid < 256) {
            unsigned a = 0;
#pragma unroll
            for (int j = 0; j < 16; j++) a += sh->hist[j][tid];
            sh->hist[0][tid] = a;
        }
        __syncthreads();
        if (warp == 0) {
            unsigned part = 0;
#pragma unroll
            for (int j = 0; j < 8; j++) part += sh->hist[0][lane * 8 + j];
            unsigned p = part;
#pragma unroll
            for (int o = 1; o < 32; o <<= 1) {
                unsigned t = __shfl_up_sync(0xffffffffu, p, o);
                if (lane >= o) p += t;
            }
            unsigned excl = p - part;
            unsigned mask = __ballot_sync(0xffffffffu, (int)excl <= rank);
            int lead = 31 - __clz(mask);
            if (lane == lead) {
                int r = rank - (int)excl;
                int d = lane * 8;
                unsigned cnt = 0;
#pragma unroll
                for (int j = 0; j < 8; j++) {
                    cnt = sh->hist[0][lane * 8 + j];
                    if (r < (int)cnt) { d = lane * 8 + j; break; }
                    r -= (int)cnt;
                }
                s_prefix = prefix | ((unsigned)d << shift);
                s_rank   = r;
                s_eq     = cnt;
            }
        }
        __syncthreads();
        prefix = s_prefix;
        rank   = s_rank;
    }

    unsigned k0 = prefix;
    float v0 = k2f(k0), v1;
    if ((unsigned)(rank + 1) < s_eq) {
        v1 = v0;
    } else {
        unsigned m = 0xFFFFFFFFu;
        for (int i = tid; i < NSEL; i += 1024) {
            unsigned k = sh->keys[i];
            if (k > k0) m = min(m, k);
        }
#pragma unroll
        for (int o = 16; o; o >>= 1) m = min(m, __shfl_xor_sync(0xffffffffu, m, o));
        if (lane == 0) s_wmin[warp] = m;
        __syncthreads();
        if (tid == 0) {
            unsigned mm = s_wmin[0];
#pragma unroll
            for (int j = 1; j < 32; j++) mm = min(mm, s_wmin[j]);
            s_prefix = mm;
        }
        __syncthreads();
        v1 = k2f(s_prefix);
    }
    float med = 0.5f * (v0 + v1);

    const float inv = rsqrtf(1.0f + 1e-5f);
    for (int c = tid; c < CH; c += 1024) {
        float u0 = st[c * 3 + 0] - med;
        float u1 = st[c * 3 + 1] - med;
        float u2 = st[c * 3 + 2] - med;
        float z = (u0 * u0 * u0) * cfc_w[c * 3 + 0]
                + (u1 * u1 * u1) * cfc_w[c * 3 + 1]
                + (u2 * u2 * u2) * cfc_w[c * 3 + 2];
        z = z * inv * bn_w[c] + bn_b[c];
        g_gate[b][c] = 1.f / (1.f + expf(-z));
    }
    __syncthreads();
}

// ---------------------------------------------------------------------------
// Fused persistent kernel.
// ---------------------------------------------------------------------------
__global__ __launch_bounds__(1024) void fused(const float* __restrict__ x,
                                              float* __restrict__ out,
                                              const float* __restrict__ cfc_w,
                                              const float* __restrict__ bn_w,
                                              const float* __restrict__ bn_b,
                                              int G) {
    __shared__ SU sh;
    int bid = blockIdx.x, tid = threadIdx.x;

    // phase1(0): all blocks, 8-channel tiles
    for (int c0 = bid * 8; c0 < CH; c0 += G * 8)
        stats_tile(x, 0, c0, sh.red);
    gbar(G);

    for (int b = 0; b < BATCH; b++) {
        if (bid == 0) {
            median_gate(b, &sh.med, cfc_w, bn_w, bn_b);
        } else if (b + 1 < BATCH) {
            for (int c0 = (bid - 1) * 8; c0 < CH; c0 += (G - 1) * 8)
                stats_tile(x, b + 1, c0, sh.red);
        }
        gbar(G);

        // phase3(b): out = x * g, channel-strided, 4-way unrolled (MLP=4).
        const float4* px = reinterpret_cast<const float4*>(x)
                         + (size_t)b * CH * (HW / 4);
        float4* po = reinterpret_cast<float4*>(out) + (size_t)b * CH * (HW / 4);
        for (int c0 = bid; c0 < CH; c0 += 4 * G) {
            float4 v[4]; float g[4]; int c[4]; bool ok[4];
#pragma unroll
            for (int j = 0; j < 4; j++) {
                c[j]  = c0 + j * G;
                ok[j] = c[j] < CH;
                if (ok[j]) {
                    g[j] = g_gate[b][c[j]];
                    v[j] = __ldcs(px + (size_t)c[j] * (HW / 4) + tid);
                }
            }
#pragma unroll
            for (int j = 0; j < 4; j++) {
                if (ok[j]) {
                    v[j].x *= g[j]; v[j].y *= g[j]; v[j].z *= g[j]; v[j].w *= g[j];
                    __stcs(po + (size_t)c[j] * (HW / 4) + tid, v[j]);
                }
            }
        }
        // no barrier needed before next iteration's phase1 (disjoint data)
    }
}

extern "C" void kernel_launch(void* const* d_in, const int* in_sizes, int n_in,
                              void* d_out, int out_size) {
    const float* x     = (const float*)d_in[0];
    const float* cfc_w = (const float*)d_in[1];
    const float* bn_w  = (const float*)d_in[2];
    const float* bn_b  = (const float*)d_in[3];
    float* out = (float*)d_out;

    int dev = 0;
    cudaGetDevice(&dev);
    int sms = 148;
    cudaDeviceGetAttribute(&sms, cudaDevAttrMultiProcessorCount, dev);
    int bpm = 1;
    cudaOccupancyMaxActiveBlocksPerMultiprocessor(&bpm, fused, 1024, 0);
    if (bpm < 1) bpm = 1;
    int G = sms * bpm;
    if (G > 512) G = 512;
    if (G < 2)   G = 2;

    fused<<<G, 1024>>>(x, out, cfc_w, bn_w, bn_b, G);
}